// round 3
// baseline (speedup 1.0000x reference)
#include <cuda_runtime.h>

// Conv2D valid cross-correlation: x[4096,4096] fp32 * w[15,15] + bias -> out[4082,4082]
//
// v3: fp32 packed-pair FFMA2 via PTX fma.rn.f32x2.
//  - even input pairs loaded directly as ulonglong2 from smem (no pack MOVs)
//  - odd pairs built with 2 MOVs from adjacent even pairs
//  - weights (w,w)-duplicated in smem, rows padded to 16 u64, LDS.128 broadcast
//  - block 256 thr, output tile 128x * 64y, thread = 8x * 4y outputs
//    (4-row y-reuse: 18 input rows feed 4 output rows -> 1.78x less LDS/output)

#define Hd 4096
#define Wd 4096
#define KHd 15
#define KWd 15
#define OHd (Hd - KHd + 1)   // 4082
#define OWd (Wd - KWd + 1)   // 4082

#define BXo 128
#define BYo 64
#define RY 4                          // output rows per thread
#define TILE_ROWS (BYo + KHd - 1)     // 78
#define SSTR 148                      // floats per smem row (>=142, mult of 4)
#define WSTR 16                       // padded weight-row entries (u64)

typedef unsigned long long u64;

__device__ __forceinline__ u64 pack2(float lo, float hi) {
    u64 r;
    asm("mov.b64 %0, {%1, %2};" : "=l"(r) : "f"(lo), "f"(hi));
    return r;
}

__device__ __forceinline__ u64 fma2(u64 a, u64 b, u64 c) {
    u64 d;
    asm("fma.rn.f32x2 %0, %1, %2, %3;" : "=l"(d) : "l"(a), "l"(b), "l"(c));
    return d;
}

// odd pair = {hi(a), lo(b)} : exactly 2 SASS MOVs
__device__ __forceinline__ u64 mkodd(u64 a, u64 b) {
    u64 r;
    asm("{\n\t"
        ".reg .b32 al, ah, bl, bh;\n\t"
        "mov.b64 {al, ah}, %1;\n\t"
        "mov.b64 {bl, bh}, %2;\n\t"
        "mov.b64 %0, {ah, bl};\n\t"
        "}" : "=l"(r) : "l"(a), "l"(b));
    return r;
}

// One ky-row of the stencil applied to 4 output pairs of one output row.
// sw2: padded weight row (16 u64, entry kx = (w,w)); warp-uniform LDS.128.
__device__ __forceinline__ void conv_row(u64 acc[4],
                                         const u64* __restrict__ sw2,
                                         const u64 ev[12],
                                         const u64 od[10]) {
#pragma unroll
    for (int i = 0; i < 8; ++i) {
        ulonglong2 w = *(const ulonglong2*)(sw2 + 2 * i);   // kx = 2i, 2i+1
#pragma unroll
        for (int p = 0; p < 4; ++p)
            acc[p] = fma2(ev[i + p], w.x, acc[p]);
        if (2 * i + 1 < KWd) {
#pragma unroll
            for (int p = 0; p < 4; ++p)
                acc[p] = fma2(od[i + p], w.y, acc[p]);
        }
    }
}

// Load 12 even pairs (direct ulonglong2) and derive 10 odd pairs (2 MOVs each).
__device__ __forceinline__ void load_row(const float* __restrict__ srow,
                                         u64 ev[12], u64 od[10]) {
#pragma unroll
    for (int i = 0; i < 6; ++i) {
        ulonglong2 v = ((const ulonglong2*)srow)[i];
        ev[2 * i + 0] = v.x;
        ev[2 * i + 1] = v.y;
    }
#pragma unroll
    for (int j = 0; j < 10; ++j)
        od[j] = mkodd(ev[j], ev[j + 1]);
}

__global__ __launch_bounds__(256, 2)
void conv2d_f32x2_kernel(const float* __restrict__ x,
                         const float* __restrict__ wt,
                         const float* __restrict__ bias,
                         float* __restrict__ out) {
    __shared__ float s_in[TILE_ROWS * SSTR];
    __shared__ u64 s_w2[KHd * WSTR];

    const int tid = threadIdx.x;
    const int tx0 = blockIdx.x * BXo;
    const int ty0 = blockIdx.y * BYo;

    // (w,w)-duplicate weights into padded rows (LDS.128-friendly).
    if (tid < KHd * KWd) {
        int r = tid / KWd;
        int c = tid - r * KWd;
        float w = wt[tid];
        s_w2[r * WSTR + c] = pack2(w, w);
    }

    // Stage input tile: 78 rows x 148 floats (cols 144..147 unstaged; never read).
    for (int s = tid; s < TILE_ROWS * 36; s += 256) {
        int rr = s / 36;
        int cc = (s - rr * 36) * 4;
        int gy = ty0 + rr;
        int gx = tx0 + cc;
        float4 v;
        if (gy < Hd && gx + 3 < Wd) {
            v = *(const float4*)(x + (size_t)gy * Wd + gx);
        } else {
            v.x = (gy < Hd && gx + 0 < Wd) ? x[(size_t)gy * Wd + gx + 0] : 0.f;
            v.y = (gy < Hd && gx + 1 < Wd) ? x[(size_t)gy * Wd + gx + 1] : 0.f;
            v.z = (gy < Hd && gx + 2 < Wd) ? x[(size_t)gy * Wd + gx + 2] : 0.f;
            v.w = (gy < Hd && gx + 3 < Wd) ? x[(size_t)gy * Wd + gx + 3] : 0.f;
        }
        *(float4*)&s_in[rr * SSTR + cc] = v;
    }
    __syncthreads();

    const int tx = tid & 15;
    const int ty = tid >> 4;
    const int oxl = tx * 8;        // local output x base (8 outputs)
    const int oyl = ty * RY;       // local output y base (4 outputs)

    const float b = bias[0];
    const u64 b2 = pack2(b, b);
    u64 acc[RY][4];
#pragma unroll
    for (int j = 0; j < RY; ++j)
#pragma unroll
        for (int p = 0; p < 4; ++p) acc[j][p] = b2;

    u64 ev[12], od[10];

    // Prologue: r = 0..2 (output row j active iff j <= r)
#pragma unroll
    for (int r = 0; r < RY - 1; ++r) {
        load_row(&s_in[(oyl + r) * SSTR + oxl], ev, od);
#pragma unroll
        for (int j = 0; j < RY; ++j)
            if (j <= r)
                conv_row(acc[j], &s_w2[(r - j) * WSTR], ev, od);
    }

    // Steady: r = 3..14 -> all RY output rows active (ky = r-j in [0,14])
#pragma unroll 1
    for (int r = RY - 1; r < KHd; ++r) {
        load_row(&s_in[(oyl + r) * SSTR + oxl], ev, od);
        const u64* wr = &s_w2[r * WSTR];
#pragma unroll
        for (int j = 0; j < RY; ++j)
            conv_row(acc[j], wr - j * WSTR, ev, od);
    }

    // Epilogue: r = 15..17 (output row j active iff r - j <= 14)
#pragma unroll
    for (int r = KHd; r < KHd + RY - 1; ++r) {
        load_row(&s_in[(oyl + r) * SSTR + oxl], ev, od);
#pragma unroll
        for (int j = 0; j < RY; ++j)
            if (r - j <= KHd - 1 && j >= 1)   // j >= r-14
                if (r - j >= 0 && r - j <= 14 && j > r - KHd)
                    ;
        // explicit active set: j in [r-14, RY-1]
#pragma unroll
        for (int j = 0; j < RY; ++j)
            if (j >= r - (KHd - 1))
                conv_row(acc[j], &s_w2[(r - j) * WSTR], ev, od);
    }

    // Store: even-aligned 8B pairs; OW=4082 even -> pairs never straddle rows.
    const int oxg = tx0 + oxl;
#pragma unroll
    for (int j = 0; j < RY; ++j) {
        int oy = ty0 + oyl + j;
        if (oy < OHd) {
            float* orow = out + (size_t)oy * OWd;
#pragma unroll
            for (int p = 0; p < 4; ++p) {
                int ox = oxg + 2 * p;
                if (ox < OWd) {
                    *(u64*)(orow + ox) = acc[j][p];
                }
            }
        }
    }
}

extern "C" void kernel_launch(void* const* d_in, const int* in_sizes, int n_in,
                              void* d_out, int out_size) {
    const float* x    = (const float*)d_in[0];
    const float* wt   = (const float*)d_in[1];
    const float* bias = (const float*)d_in[2];
    float* out        = (float*)d_out;

    dim3 grid((OWd + BXo - 1) / BXo, (OHd + BYo - 1) / BYo);  // (32, 64)
    conv2d_f32x2_kernel<<<grid, 256>>>(x, wt, bias, out);
}

// round 4
// speedup vs baseline: 1.5258x; 1.5258x over previous
#include <cuda_runtime.h>

// Conv2D valid cross-correlation: x[4096,4096] fp32 * w[15,15] + bias -> out[4082,4082]
//
// v4: fp32 packed FFMA2 (PTX fma.rn.f32x2), weights in __constant__ memory.
//  - weights stored as (w,w) u64 pairs in cmem, built by 2 strided D2D memcpys
//    at launch -> kernel reads them via LDCU (uniform path, NOT the GPR file),
//    cutting FFMA2 GPR reads from 3-even/3-odd to 2/2 (RF-bank rt 3 -> 2)
//  - even input pairs loaded directly as ulonglong2 from smem (no pack MOVs)
//  - odd pairs built with 2 MOVs from adjacent even pairs
//  - block 256 thr, output tile 128x * 32y, thread = 8x * 2y outputs

#define Hd 4096
#define Wd 4096
#define KHd 15
#define KWd 15
#define OHd (Hd - KHd + 1)   // 4082
#define OWd (Wd - KWd + 1)   // 4082

#define BXo 128
#define BYo 32
#define TILE_ROWS (BYo + KHd - 1)   // 46
#define SSTR 148                     // floats per smem row (>=142, mult of 4)

typedef unsigned long long u64;

__constant__ u64 c_w2[KHd * KWd];    // (w,w) duplicated pairs, row-major 15x15

__device__ __forceinline__ u64 pack2(float lo, float hi) {
    u64 r;
    asm("mov.b64 %0, {%1, %2};" : "=l"(r) : "f"(lo), "f"(hi));
    return r;
}

__device__ __forceinline__ u64 fma2(u64 a, u64 b, u64 c) {
    u64 d;
    asm("fma.rn.f32x2 %0, %1, %2, %3;" : "=l"(d) : "l"(a), "l"(b), "l"(c));
    return d;
}

// odd pair = {hi(a), lo(b)} : exactly 2 SASS MOVs
__device__ __forceinline__ u64 mkodd(u64 a, u64 b) {
    u64 r;
    asm("{\n\t"
        ".reg .b32 al, ah, bl, bh;\n\t"
        "mov.b64 {al, ah}, %1;\n\t"
        "mov.b64 {bl, bh}, %2;\n\t"
        "mov.b64 %0, {ah, bl};\n\t"
        "}" : "=l"(r) : "l"(a), "l"(b));
    return r;
}

// One ky-row of the stencil applied to 4 output pairs of one output row.
// wrow: pointer into c_w2 for this ky (warp-uniform -> LDCU).
__device__ __forceinline__ void conv_row(u64 acc[4],
                                         const u64* __restrict__ wrow,
                                         const u64 ev[12],
                                         const u64 od[10]) {
#pragma unroll
    for (int kx = 0; kx < KWd; ++kx) {
        u64 w2 = wrow[kx];   // cmem, uniform: LDCU -> UR operand
        if ((kx & 1) == 0) {
#pragma unroll
            for (int p = 0; p < 4; ++p)
                acc[p] = fma2(ev[(kx >> 1) + p], w2, acc[p]);
        } else {
#pragma unroll
            for (int p = 0; p < 4; ++p)
                acc[p] = fma2(od[(kx >> 1) + p], w2, acc[p]);
        }
    }
}

// Load 12 even pairs (direct ulonglong2) and derive 10 odd pairs (2 MOVs each).
__device__ __forceinline__ void load_row(const float* __restrict__ srow,
                                         u64 ev[12], u64 od[10]) {
#pragma unroll
    for (int i = 0; i < 6; ++i) {
        ulonglong2 v = ((const ulonglong2*)srow)[i];
        ev[2 * i + 0] = v.x;
        ev[2 * i + 1] = v.y;
    }
#pragma unroll
    for (int j = 0; j < 10; ++j)
        od[j] = mkodd(ev[j], ev[j + 1]);
}

__global__ __launch_bounds__(256, 3)
void conv2d_f32x2_kernel(const float* __restrict__ x,
                         const float* __restrict__ bias,
                         float* __restrict__ out) {
    __shared__ float s_in[TILE_ROWS * SSTR];

    const int tid = threadIdx.x;
    const int tx0 = blockIdx.x * BXo;
    const int ty0 = blockIdx.y * BYo;

    // Stage input tile: 46 rows x 148 floats (cols 144..147 unstaged; never read).
    for (int s = tid; s < TILE_ROWS * 36; s += 256) {
        int rr = s / 36;
        int cc = (s - rr * 36) * 4;
        int gy = ty0 + rr;
        int gx = tx0 + cc;
        float4 v;
        if (gy < Hd && gx + 3 < Wd) {
            v = *(const float4*)(x + (size_t)gy * Wd + gx);
        } else {
            v.x = (gy < Hd && gx + 0 < Wd) ? x[(size_t)gy * Wd + gx + 0] : 0.f;
            v.y = (gy < Hd && gx + 1 < Wd) ? x[(size_t)gy * Wd + gx + 1] : 0.f;
            v.z = (gy < Hd && gx + 2 < Wd) ? x[(size_t)gy * Wd + gx + 2] : 0.f;
            v.w = (gy < Hd && gx + 3 < Wd) ? x[(size_t)gy * Wd + gx + 3] : 0.f;
        }
        *(float4*)&s_in[rr * SSTR + cc] = v;
    }
    __syncthreads();

    const int tx = tid & 15;
    const int ty = tid >> 4;
    const int oxl = tx * 8;   // local output x base (8 outputs)
    const int oyl = ty * 2;   // local output y base (2 outputs)

    const float b = bias[0];
    const u64 b2 = pack2(b, b);
    u64 acc0[4] = {b2, b2, b2, b2};
    u64 acc1[4] = {b2, b2, b2, b2};

    u64 ev[12], od[10];

    // r = 0: only output row 0 (ky = 0)
    load_row(&s_in[(oyl + 0) * SSTR + oxl], ev, od);
    conv_row(acc0, &c_w2[0], ev, od);

    // r = 1..14: both output rows (ky = r for row0, ky = r-1 for row1)
#pragma unroll 1
    for (int r = 1; r <= 14; ++r) {
        load_row(&s_in[(oyl + r) * SSTR + oxl], ev, od);
        const u64* wr = &c_w2[r * KWd];
        conv_row(acc0, wr, ev, od);
        conv_row(acc1, wr - KWd, ev, od);
    }

    // r = 15: only output row 1 (ky = 14)
    load_row(&s_in[(oyl + 15) * SSTR + oxl], ev, od);
    conv_row(acc1, &c_w2[14 * KWd], ev, od);

    // Store: even-aligned 8B pairs; OW=4082 even -> pairs never straddle rows.
    const int oxg = tx0 + oxl;
#pragma unroll
    for (int ry = 0; ry < 2; ++ry) {
        int oy = ty0 + oyl + ry;
        if (oy < OHd) {
            const u64* accp = ry ? acc1 : acc0;
            float* orow = out + (size_t)oy * OWd;
#pragma unroll
            for (int p = 0; p < 4; ++p) {
                int ox = oxg + 2 * p;
                if (ox < OWd) {
                    *(u64*)(orow + ox) = accp[p];
                }
            }
        }
    }
}

extern "C" void kernel_launch(void* const* d_in, const int* in_sizes, int n_in,
                              void* d_out, int out_size) {
    const float* x    = (const float*)d_in[0];
    const float* wt   = (const float*)d_in[1];
    const float* bias = (const float*)d_in[2];
    float* out        = (float*)d_out;

    // Build (w,w) u64 pairs in __constant__ memory with two strided D2D copies.
    // Graph-capturable (async D2D), no allocation.
    void* cw_addr = nullptr;
    cudaGetSymbolAddress(&cw_addr, c_w2);
    // low half of each pair
    cudaMemcpy2DAsync(cw_addr, 8, wt, 4, 4, KHd * KWd,
                      cudaMemcpyDeviceToDevice, 0);
    // high half of each pair
    cudaMemcpy2DAsync((char*)cw_addr + 4, 8, wt, 4, 4, KHd * KWd,
                      cudaMemcpyDeviceToDevice, 0);

    dim3 grid((OWd + BXo - 1) / BXo, (OHd + BYo - 1) / BYo);  // (32, 128)
    conv2d_f32x2_kernel<<<grid, 256>>>(x, bias, out);
}